// round 15
// baseline (speedup 1.0000x reference)
#include <cuda_runtime.h>
#include <cuda_bf16.h>
#include <cuda_fp16.h>
#include <math.h>
#include <stdint.h>

#define DF 4096
#define LL 24
#define NTOK 576
#define TT 128
#define RR 1024
#define STOT (LL*NTOK)   // 13824
#define NH 8
#define HDIM 512
#define NSPL2 8
#define KS2 (STOT/NSPL2)   // 1728
#define QSPL 8
#define QKS (DF/QSPL)      // 512

// ---------------- scratch (device globals) ----------------
__device__ __align__(256) float g_tg[DF];
__device__ __align__(256) float g_y[LL*DF];
__device__ __align__(256) float g_base[LL*RR];
__device__ __align__(256) float g_c[DF];
__device__ __align__(256) float g_cpn[DF];
__device__ __align__(256) float g_s[RR];
__device__ __align__(256) float g_ctx[LL*DF];
__device__ __align__(256) float g_scores[(size_t)NH*TT*STOT];
__device__ __align__(256) float g_qpart[QSPL*TT*DF];
__device__ __align__(256) float g_opart[QSPL*TT*DF];
__device__ __align__(256) float g_avpart[(size_t)NSPL2*TT*DF];
// fp16 staging
__device__ __align__(256) __half g_w1h[(size_t)DF*DF];
__device__ __align__(256) __half g_w2h[(size_t)DF*DF];
__device__ __align__(256) __half g_wkh[(size_t)DF*DF];
__device__ __align__(256) __half g_wqh[(size_t)DF*DF];
__device__ __align__(256) __half g_woh[(size_t)DF*DF];
__device__ __align__(256) __half g_xh[(size_t)STOT*DF];     // X for g1; reused as pre-K
__device__ __align__(256) __half g_hh[(size_t)STOT*DF];
__device__ __align__(256) __half g_rh[(size_t)STOT*DF];
__device__ __align__(256) __half g_rhT[(size_t)DF*STOT];
__device__ __align__(256) __half g_kh[(size_t)STOT*DF];
__device__ __align__(256) __half g_qh[(size_t)TT*DF];
__device__ __align__(256) __half g_texth[(size_t)TT*DF];
__device__ __align__(256) __half g_atth[(size_t)TT*DF];
__device__ __align__(256) __half g_attnh[(size_t)NH*TT*STOT];
__device__ __align__(256) __half g_w1b0h[(size_t)RR*DF];
__device__ __align__(256) __half g_wch[(size_t)DF*RR];
__device__ __align__(256) __half g_wih[(size_t)DF*RR];
__device__ __align__(256) __half g_wfh[(size_t)DF*RR];

// ---------------- helpers ----------------
__device__ __forceinline__ void cpa16h(__half* s, const __half* g){
    uint32_t a = (uint32_t)__cvta_generic_to_shared(s);
    asm volatile("cp.async.cg.shared.global [%0], [%1], 16;\n" :: "r"(a), "l"(g));
}
__device__ __forceinline__ float warp_sum(float v){
    #pragma unroll
    for (int o=16;o;o>>=1) v += __shfl_down_sync(0xffffffffu, v, o);
    return v;
}
__device__ __forceinline__ float sigf(float x){ return 1.f/(1.f+expf(-x)); }
__device__ __forceinline__ float dot8h(uint4 w, const float* c){
    float2 f0 = __half22float2(*reinterpret_cast<__half2*>(&w.x));
    float2 f1 = __half22float2(*reinterpret_cast<__half2*>(&w.y));
    float2 f2 = __half22float2(*reinterpret_cast<__half2*>(&w.z));
    float2 f3 = __half22float2(*reinterpret_cast<__half2*>(&w.w));
    float4 c0 = *reinterpret_cast<const float4*>(c);
    float4 c1 = *reinterpret_cast<const float4*>(c + 4);
    return f0.x*c0.x + f0.y*c0.y + f1.x*c0.z + f1.y*c0.w
         + f2.x*c1.x + f2.y*c1.y + f3.x*c1.z + f3.y*c1.w;
}

// ============ fp16 GEMM: C[M,N] = A[M,K] @ B[N,K]^T, half in, fp32 accum ============
// CTA 128x256, warp 64x64 (8 warps 2x4), BK=64, 3-stage cp.async ring + ldmatrix.
// Final tile drains with wait_group 0 (race fix: newest group may be the tile being consumed).
// EPI 0: Cf=acc*alpha ; 1: Ch=half(gelu(acc+bias)) ; 2: Ch=half(extra*sig(acc+bias)) ; 3: Ch=half(acc*alpha)
#define HBK 64
#define HPAD 72
#define HASZ (128*HPAD)
#define HBSZ (256*HPAD)
#define HSTG 3
#define HSMEM (HSTG*(HASZ + HBSZ)*2)     // 165888 bytes

template<int EPI>
__global__ void __launch_bounds__(256, 1) gemm_h(
    const __half* __restrict__ A, int lda,
    const __half* __restrict__ B, int ldb,
    float* __restrict__ Cf, __half* __restrict__ Ch, int ldc,
    int Kdim, int zDiv,
    size_t aSh, size_t aSp, size_t bSh, size_t bSp, size_t cSh, size_t cSp,
    const float* __restrict__ bias, const float* __restrict__ extra,
    float alpha)
{
    extern __shared__ __half smh[];
    __half* As = smh;                    // [HSTG][128][HPAD]
    __half* Bs = smh + HSTG*HASZ;        // [HSTG][256][HPAD]

    const int zh = blockIdx.z / zDiv, zp = blockIdx.z % zDiv;
    A += (size_t)zh*aSh + (size_t)zp*aSp;
    B += (size_t)zh*bSh + (size_t)zp*bSp;
    const size_t coff = (size_t)zh*cSh + (size_t)zp*cSp;

    const int tid = threadIdx.x, lane = tid & 31, warp = tid >> 5;
    const int wm = warp >> 2, wn = warp & 3;
    const int g = lane >> 2, t = lane & 3;
    const int m0 = blockIdx.y * 128, n0 = blockIdx.x * 256;

    const uint32_t As_u = (uint32_t)__cvta_generic_to_shared(As);
    const uint32_t Bs_u = (uint32_t)__cvta_generic_to_shared(Bs);
    const uint32_t a_off = (uint32_t)(((wm*64 + (lane & 15))*HPAD + (lane >> 4)*8) * 2);
    const uint32_t b_off = (uint32_t)(((wn*64 + ((lane >> 4) << 3) + (lane & 7))*HPAD + ((lane >> 3) & 1)*8) * 2);

    float acc[4][8][4];
    #pragma unroll
    for (int i=0;i<4;i++)
        #pragma unroll
        for (int j=0;j<8;j++)
            #pragma unroll
            for (int e=0;e<4;e++) acc[i][j][e]=0.f;

    auto loadT = [&](int kt, int b){
        #pragma unroll
        for (int i=0;i<4;i++){
            int c = tid + i*256; int row = c>>3, k8 = c&7;
            cpa16h(As + b*HASZ + row*HPAD + k8*8,
                   A + (size_t)(m0+row)*lda + kt*HBK + k8*8);
        }
        #pragma unroll
        for (int i=0;i<8;i++){
            int c = tid + i*256; int row = c>>3, k8 = c&7;
            cpa16h(Bs + b*HBSZ + row*HPAD + k8*8,
                   B + (size_t)(n0+row)*ldb + kt*HBK + k8*8);
        }
        asm volatile("cp.async.commit_group;\n");
    };

    const int nk = Kdim/HBK;
    loadT(0, 0);
    loadT(1, 1);

    int slot = 0;
    for (int kt=0; kt<nk; kt++){
        if (kt+1 < nk){
            asm volatile("cp.async.wait_group 1;\n");
        } else {
            asm volatile("cp.async.wait_group 0;\n");   // drain: newest group is THIS tile
        }
        __syncthreads();

        const uint32_t Au = As_u + (uint32_t)(slot*HASZ*2);
        const uint32_t Bu = Bs_u + (uint32_t)(slot*HBSZ*2);
        #pragma unroll
        for (int ks=0; ks<4; ks++){
            uint32_t af[4][4], bf[8][2];
            #pragma unroll
            for (int mi=0;mi<4;mi++){
                uint32_t ad = Au + a_off + (uint32_t)(mi*16*HPAD*2 + ks*32);
                asm volatile("ldmatrix.sync.aligned.m8n8.x4.shared.b16 {%0,%1,%2,%3}, [%4];"
                    : "=r"(af[mi][0]),"=r"(af[mi][1]),"=r"(af[mi][2]),"=r"(af[mi][3]) : "r"(ad));
            }
            #pragma unroll
            for (int np=0;np<4;np++){
                uint32_t bd = Bu + b_off + (uint32_t)(np*16*HPAD*2 + ks*32);
                asm volatile("ldmatrix.sync.aligned.m8n8.x4.shared.b16 {%0,%1,%2,%3}, [%4];"
                    : "=r"(bf[2*np][0]),"=r"(bf[2*np][1]),"=r"(bf[2*np+1][0]),"=r"(bf[2*np+1][1]) : "r"(bd));
            }
            #pragma unroll
            for (int mi=0;mi<4;mi++)
                #pragma unroll
                for (int ni=0;ni<8;ni++)
                    asm volatile(
                        "mma.sync.aligned.m16n8k16.row.col.f32.f16.f16.f32 "
                        "{%0,%1,%2,%3},{%4,%5,%6,%7},{%8,%9},{%0,%1,%2,%3};\n"
                        : "+f"(acc[mi][ni][0]), "+f"(acc[mi][ni][1]),
                          "+f"(acc[mi][ni][2]), "+f"(acc[mi][ni][3])
                        : "r"(af[mi][0]),"r"(af[mi][1]),"r"(af[mi][2]),"r"(af[mi][3]),
                          "r"(bf[ni][0]),"r"(bf[ni][1]));
        }

        if (kt+2 < nk){
            int s2 = slot + 2; if (s2 >= HSTG) s2 -= HSTG;
            loadT(kt+2, s2);
        }
        if (++slot == HSTG) slot = 0;
    }

    #pragma unroll
    for (int mi=0;mi<4;mi++){
        #pragma unroll
        for (int half_=0; half_<2; half_++){
            const int row = m0 + wm*64 + mi*16 + g + half_*8;
            #pragma unroll
            for (int ni=0;ni<8;ni++){
                const int col = n0 + wn*64 + ni*8 + t*2;
                float v0 = acc[mi][ni][half_*2 + 0];
                float v1 = acc[mi][ni][half_*2 + 1];
                if (EPI==0){
                    float2 o; o.x=v0*alpha; o.y=v1*alpha;
                    *reinterpret_cast<float2*>(Cf + coff + (size_t)row*ldc + col) = o;
                } else if (EPI==1){
                    float x0 = v0 + bias[col], x1 = v1 + bias[col+1];
                    float o0 = 0.5f*x0*(1.f + erff(x0*0.70710678118654752f));
                    float o1 = 0.5f*x1*(1.f + erff(x1*0.70710678118654752f));
                    *reinterpret_cast<__half2*>(Ch + coff + (size_t)row*ldc + col) = __floats2half2_rn(o0, o1);
                } else if (EPI==2){
                    float x0 = v0 + bias[col], x1 = v1 + bias[col+1];
                    const float2 ex = *reinterpret_cast<const float2*>(extra + (size_t)row*DF + col);
                    *reinterpret_cast<__half2*>(Ch + coff + (size_t)row*ldc + col) =
                        __floats2half2_rn(ex.x * sigf(x0), ex.y * sigf(x1));
                } else {
                    *reinterpret_cast<__half2*>(Ch + coff + (size_t)row*ldc + col) =
                        __floats2half2_rn(v0*alpha, v1*alpha);
                }
            }
        }
    }
}

// ---------------- small kernels ----------------
__global__ void w2h_kernel(const float* __restrict__ w, __half* __restrict__ o){
    size_t i = ((size_t)blockIdx.x*256 + threadIdx.x)*4;
    float4 v = *reinterpret_cast<const float4*>(w + i);
    *reinterpret_cast<__half2*>(o + i)     = __floats2half2_rn(v.x, v.y);
    *reinterpret_cast<__half2*>(o + i + 2) = __floats2half2_rn(v.z, v.w);
}

__global__ void w1b0_kernel(const float* __restrict__ W1w, __half* __restrict__ o){
    size_t e = ((size_t)blockIdx.x*256 + threadIdx.x)*4;
    int r = (int)(e / DF), c = (int)(e % DF);
    float4 v = *reinterpret_cast<const float4*>(W1w + (size_t)r*3*DF + c);
    *reinterpret_cast<__half2*>(o + e)     = __floats2half2_rn(v.x, v.y);
    *reinterpret_cast<__half2*>(o + e + 2) = __floats2half2_rn(v.z, v.w);
}

__global__ void tr_kernel(const __half* __restrict__ in, __half* __restrict__ out){
    __shared__ __half sm[64][68];
    const int s0 = blockIdx.x*64, d0 = blockIdx.y*64;
    const int tid = threadIdx.x;
    #pragma unroll
    for (int p=0;p<2;p++){
        int r = (tid>>3) + p*32;
        int cg = tid & 7;
        uint4 v = *reinterpret_cast<const uint4*>(in + (size_t)(s0+r)*DF + d0 + cg*8);
        uint2* dst = reinterpret_cast<uint2*>(&sm[r][cg*8]);
        dst[0] = make_uint2(v.x, v.y);
        dst[1] = make_uint2(v.z, v.w);
    }
    __syncthreads();
    #pragma unroll
    for (int p=0;p<2;p++){
        int dl = (tid>>3) + p*32;
        int cg = tid & 7;
        __half tmp[8];
        #pragma unroll
        for (int i=0;i<8;i++) tmp[i] = sm[cg*8 + i][dl];
        *reinterpret_cast<uint4*>(out + (size_t)(d0+dl)*STOT + s0 + cg*8) =
            *reinterpret_cast<uint4*>(tmp);
    }
}

__global__ void reduce_text_kernel(const float* __restrict__ text){
    int d = blockIdx.x*256 + threadIdx.x;
    float s = 0.f;
    for (int tt=0; tt<TT; tt++) s += text[(size_t)tt*DF + d];
    g_tg[d] = s * (1.f/TT);
}

__global__ void reduce_feats_kernel(const float* __restrict__ feats){
    int d = blockIdx.x*256 + threadIdx.x;
    int l = blockIdx.y;
    const float* p = feats + (size_t)l*NTOK*DF + d;
    float s = 0.f;
    for (int n=0;n<NTOK;n++) s += p[(size_t)n*DF];
    g_y[l*DF + d] = s * (1.f/NTOK);
}

__global__ void base_kernel(const float* __restrict__ W1w, const float* __restrict__ W1b){
    int warp = threadIdx.x >> 5, lane = threadIdx.x & 31;
    int r = blockIdx.x*8 + warp;
    int l = blockIdx.y;
    const float* wy = W1w + (size_t)r*(3*DF) + DF;
    const float* wt = wy + DF;
    const float* y  = g_y + l*DF;
    float acc = 0.f;
    for (int j = lane*4; j < DF; j += 128){
        float4 a = *(const float4*)(wy + j);
        float4 b = *(const float4*)(y + j);
        acc += a.x*b.x + a.y*b.y + a.z*b.z + a.w*b.w;
        float4 c = *(const float4*)(wt + j);
        float4 d = *(const float4*)(g_tg + j);
        acc += c.x*d.x + c.y*d.y + c.z*d.z + c.w*d.w;
    }
    acc = warp_sum(acc);
    if (lane==0) g_base[l*RR + r] = acc + W1b[r];
}

__global__ void dsu_init_kernel(){
    int i = blockIdx.x*256 + threadIdx.x;
    g_c[i] = 0.f; g_cpn[i] = 0.5f;
}

__global__ void s_kernel(int l){
    int r = blockIdx.x*8 + (threadIdx.x>>5);
    int lane = threadIdx.x & 31;
    const __half* w = g_w1b0h + (size_t)r*DF;
    float acc = 0.f;
    for (int j=lane*8; j<DF; j+=256)
        acc += dot8h(*reinterpret_cast<const uint4*>(w + j), g_cpn + j);
    acc = warp_sum(acc);
    if (lane==0){ float v = acc + g_base[l*RR + r]; g_s[r] = v > 0.f ? v : 0.f; }
}

__global__ void c_kernel(const float* __restrict__ Wcb, const float* __restrict__ bc,
                         const float* __restrict__ Wib, const float* __restrict__ bi,
                         const float* __restrict__ Wfb, const float* __restrict__ bfb,
                         int l){
    int d = blockIdx.x*8 + (threadIdx.x>>5);
    int lane = threadIdx.x & 31;
    float ac=0.f, ai=0.f, afv=0.f;
    for (int j=lane*8; j<RR; j+=256){
        ac  += dot8h(*reinterpret_cast<const uint4*>(g_wch + (size_t)d*RR + j), g_s + j);
        ai  += dot8h(*reinterpret_cast<const uint4*>(g_wih + (size_t)d*RR + j), g_s + j);
        afv += dot8h(*reinterpret_cast<const uint4*>(g_wfh + (size_t)d*RR + j), g_s + j);
    }
    ac = warp_sum(ac); ai = warp_sum(ai); afv = warp_sum(afv);
    if (lane==0){
        float ct = tanhf(ac + Wcb[d] + bc[d]);
        float ig = sigf(ai + Wib[d] + bi[d]);
        float fg = sigf(afv + Wfb[d] + bfb[d]);
        float cn = fg*g_c[d] + ig*ct;
        g_c[d] = cn;
        g_cpn[d] = sigf(cn);
        g_ctx[l*DF + d] = cn;
    }
}

__global__ void addctx_h_kernel(const float* __restrict__ feats){
    size_t n4 = (size_t)STOT*DF/4;
    const float4* f4 = (const float4*)feats;
    const float4* c4 = (const float4*)g_ctx;
    for (size_t i = (size_t)blockIdx.x*blockDim.x + threadIdx.x; i < n4; i += (size_t)gridDim.x*blockDim.x){
        size_t row = i >> 10;
        int l = (int)(row / NTOK);
        int d4 = (int)(i & 1023);
        float4 a = f4[i], b = c4[l*1024 + d4];
        *reinterpret_cast<__half2*>(g_xh + i*4)     = __floats2half2_rn(a.x+b.x, a.y+b.y);
        *reinterpret_cast<__half2*>(g_xh + i*4 + 2) = __floats2half2_rn(a.z+b.z, a.w+b.w);
    }
}

// LayerNorm: src fp32 (P-way partial) or srch half (P=1); out fp32 or half
__global__ void ln_kernel(const float* __restrict__ src, const __half* __restrict__ srch,
                          size_t pstride, int P,
                          const float* __restrict__ bias,
                          const float* __restrict__ gam, const float* __restrict__ bet,
                          float* __restrict__ dst, __half* __restrict__ dsth){
    int row = blockIdx.x, tid = threadIdx.x;
    float x[16];
    float s=0.f, sq=0.f;
    #pragma unroll
    for (int j=0;j<16;j++){
        int col = tid + j*256;
        size_t base = (size_t)row*DF + col;
        float v = bias[col];
        if (srch){
            v += __half2float(srch[base]);
        } else {
            for (int p=0;p<P;p++) v += src[(size_t)p*pstride + base];
        }
        x[j]=v; s+=v; sq+=v*v;
    }
    __shared__ float r1[256], r2[256];
    r1[tid]=s; r2[tid]=sq; __syncthreads();
    for (int o=128;o;o>>=1){ if(tid<o){ r1[tid]+=r1[tid+o]; r2[tid]+=r2[tid+o]; } __syncthreads(); }
    float mean = r1[0]*(1.f/DF);
    float var  = r2[0]*(1.f/DF) - mean*mean;
    float rstd = rsqrtf(var + 1e-5f);
    #pragma unroll
    for (int j=0;j<16;j++){
        int col = tid + j*256;
        float o = (x[j]-mean)*rstd*gam[col] + bet[col];
        if (dsth) dsth[(size_t)row*DF + col] = __float2half(o);
        else      dst [(size_t)row*DF + col] = o;
    }
}

__global__ void softmax_kernel(){
    int row = blockIdx.x, tid = threadIdx.x;
    const float* p = g_scores + (size_t)row*STOT;
    __half* q = g_attnh + (size_t)row*STOT;
    __shared__ float red[256];
    float m = -1e30f;
    for (int j=tid; j<STOT; j+=256) m = fmaxf(m, p[j]);
    red[tid]=m; __syncthreads();
    for (int o=128;o;o>>=1){ if(tid<o) red[tid]=fmaxf(red[tid],red[tid+o]); __syncthreads(); }
    m = red[0]; __syncthreads();
    float s = 0.f;
    for (int j=tid; j<STOT; j+=256){ s += expf(p[j]-m); }
    red[tid]=s; __syncthreads();
    for (int o=128;o;o>>=1){ if(tid<o) red[tid]+=red[tid+o]; __syncthreads(); }
    float inv = 1.f/red[0];
    for (int j=tid; j<STOT; j+=256) q[j] = __float2half(expf(p[j]-m)*inv);
}

__global__ void avreduce_kernel(){
    int i = blockIdx.x*256 + threadIdx.x;
    float s = 0.f;
    #pragma unroll
    for (int p=0;p<NSPL2;p++) s += g_avpart[(size_t)p*TT*DF + i];
    g_atth[i] = __float2half(s);
}

__global__ void t2h_kernel(const float* __restrict__ in, __half* __restrict__ o){
    size_t i = ((size_t)blockIdx.x*256 + threadIdx.x)*4;
    float4 v = *reinterpret_cast<const float4*>(in + i);
    *reinterpret_cast<__half2*>(o + i)     = __floats2half2_rn(v.x, v.y);
    *reinterpret_cast<__half2*>(o + i + 2) = __floats2half2_rn(v.z, v.w);
}

// ---------------- host launch ----------------
extern "C" void kernel_launch(void* const* d_in, const int* in_sizes, int n_in,
                              void* d_out, int out_size) {
    const float* text = (const float*)d_in[0];
    const float* feats= (const float*)d_in[1];
    const float* W1_w = (const float*)d_in[2];
    const float* W1_b = (const float*)d_in[3];
    const float* Wc_w = (const float*)d_in[4];
    const float* Wc_b = (const float*)d_in[5];
    const float* Wi_w = (const float*)d_in[6];
    const float* Wi_b = (const float*)d_in[7];
    const float* Wf_w = (const float*)d_in[8];
    const float* Wf_b = (const float*)d_in[9];
    const float* bc   = (const float*)d_in[10];
    const float* bi   = (const float*)d_in[11];
    const float* bfp  = (const float*)d_in[12];
    const float* g1_w = (const float*)d_in[13];
    const float* g1_b = (const float*)d_in[14];
    const float* g2_w = (const float*)d_in[15];
    const float* g2_b = (const float*)d_in[16];
    const float* Wq_w = (const float*)d_in[17];
    const float* Wq_b = (const float*)d_in[18];
    const float* Wk_w = (const float*)d_in[19];
    const float* Wk_b = (const float*)d_in[20];
    const float* Wo_w = (const float*)d_in[21];
    const float* Wo_b = (const float*)d_in[22];
    const float* qn_g = (const float*)d_in[23];
    const float* qn_b = (const float*)d_in[24];
    const float* kn_g = (const float*)d_in[25];
    const float* kn_b = (const float*)d_in[26];
    const float* on_g = (const float*)d_in[27];
    const float* on_b = (const float*)d_in[28];
    float* out = (float*)d_out;

    float *p_scores, *p_qpart, *p_opart, *p_avpart;
    __half *p_w1h, *p_w2h, *p_wkh, *p_wqh, *p_woh, *p_xh, *p_hh, *p_rh, *p_rhT, *p_kh, *p_qh, *p_texth, *p_atth, *p_attnh;
    __half *p_w1b0h, *p_wch, *p_wih, *p_wfh;
    cudaGetSymbolAddress((void**)&p_scores, g_scores);
    cudaGetSymbolAddress((void**)&p_qpart, g_qpart);
    cudaGetSymbolAddress((void**)&p_opart, g_opart);
    cudaGetSymbolAddress((void**)&p_avpart, g_avpart);
    cudaGetSymbolAddress((void**)&p_w1h, g_w1h);
    cudaGetSymbolAddress((void**)&p_w2h, g_w2h);
    cudaGetSymbolAddress((void**)&p_wkh, g_wkh);
    cudaGetSymbolAddress((void**)&p_wqh, g_wqh);
    cudaGetSymbolAddress((void**)&p_woh, g_woh);
    cudaGetSymbolAddress((void**)&p_xh, g_xh);
    cudaGetSymbolAddress((void**)&p_hh, g_hh);
    cudaGetSymbolAddress((void**)&p_rh, g_rh);
    cudaGetSymbolAddress((void**)&p_rhT, g_rhT);
    cudaGetSymbolAddress((void**)&p_kh, g_kh);
    cudaGetSymbolAddress((void**)&p_qh, g_qh);
    cudaGetSymbolAddress((void**)&p_texth, g_texth);
    cudaGetSymbolAddress((void**)&p_atth, g_atth);
    cudaGetSymbolAddress((void**)&p_attnh, g_attnh);
    cudaGetSymbolAddress((void**)&p_w1b0h, g_w1b0h);
    cudaGetSymbolAddress((void**)&p_wch, g_wch);
    cudaGetSymbolAddress((void**)&p_wih, g_wih);
    cudaGetSymbolAddress((void**)&p_wfh, g_wfh);

    cudaFuncSetAttribute(gemm_h<0>, cudaFuncAttributeMaxDynamicSharedMemorySize, HSMEM);
    cudaFuncSetAttribute(gemm_h<1>, cudaFuncAttributeMaxDynamicSharedMemorySize, HSMEM);
    cudaFuncSetAttribute(gemm_h<2>, cudaFuncAttributeMaxDynamicSharedMemorySize, HSMEM);
    cudaFuncSetAttribute(gemm_h<3>, cudaFuncAttributeMaxDynamicSharedMemorySize, HSMEM);

    // 1) means + weight converts
    reduce_text_kernel<<<DF/256, 256>>>(text);
    reduce_feats_kernel<<<dim3(DF/256, LL), 256>>>(feats);
    base_kernel<<<dim3(RR/8, LL), 256>>>(W1_w, W1_b);
    dsu_init_kernel<<<DF/256, 256>>>();
    const int wblocks = (DF*DF/4)/256;
    w2h_kernel<<<wblocks, 256>>>(g1_w, p_w1h);
    w2h_kernel<<<wblocks, 256>>>(g2_w, p_w2h);
    w2h_kernel<<<wblocks, 256>>>(Wk_w, p_wkh);
    w2h_kernel<<<wblocks, 256>>>(Wq_w, p_wqh);
    w2h_kernel<<<wblocks, 256>>>(Wo_w, p_woh);
    t2h_kernel<<<(TT*DF/4)/256, 256>>>(text, p_texth);
    const int dblocks = (DF*RR/4)/256;
    w1b0_kernel<<<dblocks, 256>>>(W1_w, p_w1b0h);
    w2h_kernel<<<dblocks, 256>>>(Wc_w, p_wch);
    w2h_kernel<<<dblocks, 256>>>(Wi_w, p_wih);
    w2h_kernel<<<dblocks, 256>>>(Wf_w, p_wfh);

    // 2) DSU recurrence (serial, fp16 weights)
    for (int l=0; l<LL; l++){
        s_kernel<<<RR/8, 256>>>(l);
        c_kernel<<<DF/8, 256>>>(Wc_b, bc, Wi_b, bi, Wf_b, bfp, l);
    }

    // 3) spatial gate
    addctx_h_kernel<<<2048, 256>>>(feats);
    dim3 bg(DF/256, STOT/128);
    gemm_h<1><<<bg, 256, HSMEM>>>(p_xh, DF, p_w1h, DF, nullptr, p_hh, DF, DF, 1,
        0,0,0,0,0,0, g1_b, nullptr, 1.f);
    gemm_h<2><<<bg, 256, HSMEM>>>(p_hh, DF, p_w2h, DF, nullptr, p_rh, DF, DF, 1,
        0,0,0,0,0,0, g2_b, feats, 1.f);
    tr_kernel<<<dim3(STOT/64, DF/64), 256>>>(p_rh, p_rhT);

    // 4) Q projection (fp16, split-K 8) + LN -> half
    gemm_h<0><<<dim3(DF/256, 1, QSPL), 256, HSMEM>>>(
        p_texth, DF, p_wqh, DF, p_qpart, nullptr, DF, QKS, QSPL,
        0, QKS, 0, QKS, 0, (size_t)TT*DF, nullptr, nullptr, 1.f);
    ln_kernel<<<TT, 256>>>(p_qpart, nullptr, (size_t)TT*DF, QSPL, Wq_b, qn_g, qn_b, nullptr, p_qh);

    // 5) K projection (fp16, half out into xh) + LN -> half
    gemm_h<3><<<bg, 256, HSMEM>>>(p_rh, DF, p_wkh, DF, nullptr, p_xh, DF, DF, 1,
        0,0,0,0,0,0, nullptr, nullptr, 1.f);
    ln_kernel<<<STOT, 256>>>(nullptr, p_xh, 0, 1, Wk_b, kn_g, kn_b, nullptr, p_kh);

    // 6) scores = Q_h @ K_h^T / sqrt(HD*L)
    float alpha = 1.0f / sqrtf((float)HDIM * (float)LL);
    gemm_h<0><<<dim3(STOT/256, 1, NH), 256, HSMEM>>>(
        p_qh, DF, p_kh, DF, p_scores, nullptr, STOT, HDIM, 1,
        512, 0, 512, 0, (size_t)TT*STOT, 0, nullptr, nullptr, alpha);

    // 7) softmax -> half attn
    softmax_kernel<<<NH*TT, 256>>>();

    // 8) att = attn @ V  (fp16, split-K 8) -> half att
    gemm_h<0><<<dim3(HDIM/256, 1, NH*NSPL2), 256, HSMEM>>>(
        p_attnh, STOT, p_rhT, STOT, p_avpart, nullptr, DF, KS2, NSPL2,
        (size_t)TT*STOT, KS2, (size_t)HDIM*STOT, KS2, 512, (size_t)TT*DF,
        nullptr, nullptr, 1.f);
    avreduce_kernel<<<TT*DF/256, 256>>>();

    // 9) out = LN(att @ Wo^T + b)  (fp16 split-K 8)
    gemm_h<0><<<dim3(DF/256, 1, QSPL), 256, HSMEM>>>(
        p_atth, DF, p_woh, DF, p_opart, nullptr, DF, QKS, QSPL,
        0, QKS, 0, QKS, 0, (size_t)TT*DF, nullptr, nullptr, 1.f);
    ln_kernel<<<TT, 256>>>(p_opart, nullptr, (size_t)TT*DF, QSPL, Wo_b, on_g, on_b, out, nullptr);

    (void)in_sizes; (void)n_in; (void)out_size;
}

// round 17
// speedup vs baseline: 1.0114x; 1.0114x over previous
#include <cuda_runtime.h>
#include <cuda_bf16.h>
#include <cuda_fp16.h>
#include <math.h>
#include <stdint.h>

#define DF 4096
#define LL 24
#define NTOK 576
#define TT 128
#define RR 1024
#define STOT (LL*NTOK)   // 13824
#define NH 8
#define HDIM 512
#define NSPL2 8
#define KS2 (STOT/NSPL2)   // 1728
#define QSPL 8
#define QKS (DF/QSPL)      // 512

// ---------------- scratch (device globals) ----------------
__device__ __align__(256) float g_tg[DF];
__device__ __align__(256) float g_y[LL*DF];
__device__ __align__(256) float g_base[LL*RR];
__device__ __align__(256) float g_c[DF];
__device__ __align__(256) float g_cpn[DF];
__device__ __align__(256) float g_s[RR];
__device__ __align__(256) float g_ctx[LL*DF];
__device__ __align__(256) float g_qpart[QSPL*TT*DF];
__device__ __align__(256) float g_opart[QSPL*TT*DF];
__device__ __align__(256) float g_avpart[(size_t)NSPL2*TT*DF];
// fp16 staging
__device__ __align__(256) __half g_w1h[(size_t)DF*DF];
__device__ __align__(256) __half g_w2h[(size_t)DF*DF];
__device__ __align__(256) __half g_wkh[(size_t)DF*DF];
__device__ __align__(256) __half g_wqh[(size_t)DF*DF];
__device__ __align__(256) __half g_woh[(size_t)DF*DF];
__device__ __align__(256) __half g_xh[(size_t)STOT*DF];     // X for g1; reused as pre-K
__device__ __align__(256) __half g_hh[(size_t)STOT*DF];
__device__ __align__(256) __half g_rh[(size_t)STOT*DF];
__device__ __align__(256) __half g_kh[(size_t)STOT*DF];
__device__ __align__(256) __half g_qh[(size_t)TT*DF];
__device__ __align__(256) __half g_texth[(size_t)TT*DF];
__device__ __align__(256) __half g_atth[(size_t)TT*DF];
__device__ __align__(256) __half g_scoresh[(size_t)NH*TT*STOT];
__device__ __align__(256) __half g_attnh[(size_t)NH*TT*STOT];
__device__ __align__(256) __half g_w1b0h[(size_t)RR*DF];
__device__ __align__(256) __half g_wch[(size_t)DF*RR];
__device__ __align__(256) __half g_wih[(size_t)DF*RR];
__device__ __align__(256) __half g_wfh[(size_t)DF*RR];

// ---------------- helpers ----------------
__device__ __forceinline__ void cpa16h(__half* s, const __half* g){
    uint32_t a = (uint32_t)__cvta_generic_to_shared(s);
    asm volatile("cp.async.cg.shared.global [%0], [%1], 16;\n" :: "r"(a), "l"(g));
}
__device__ __forceinline__ float warp_sum(float v){
    #pragma unroll
    for (int o=16;o;o>>=1) v += __shfl_down_sync(0xffffffffu, v, o);
    return v;
}
__device__ __forceinline__ float sigf(float x){ return 1.f/(1.f+expf(-x)); }
__device__ __forceinline__ float dot8h(uint4 w, const float* c){
    float2 f0 = __half22float2(*reinterpret_cast<__half2*>(&w.x));
    float2 f1 = __half22float2(*reinterpret_cast<__half2*>(&w.y));
    float2 f2 = __half22float2(*reinterpret_cast<__half2*>(&w.z));
    float2 f3 = __half22float2(*reinterpret_cast<__half2*>(&w.w));
    float4 c0 = *reinterpret_cast<const float4*>(c);
    float4 c1 = *reinterpret_cast<const float4*>(c + 4);
    return f0.x*c0.x + f0.y*c0.y + f1.x*c0.z + f1.y*c0.w
         + f2.x*c1.x + f2.y*c1.y + f3.x*c1.z + f3.y*c1.w;
}

// ============ fp16 GEMM, half in, fp32 accum ============
// BL=0: C[M,N] = A[M,K] @ B[N,K]^T (B row-major NT).  BL=1: C[M,N] = A[M,K] @ B[K,N] (B row-major NN,
// loaded [k][n] in smem and consumed via ldmatrix.trans — fragment-identical to the NT path).
// CTA 128x256, warp 64x64 (8 warps 2x4), BK=64, 3-stage cp.async ring + ldmatrix; final tile drains fully.
// EPI 0: Cf=acc*alpha ; 1: Ch=half(gelu(acc+bias)) ; 2: Ch=half(extra*sig(acc+bias)) ; 3: Ch=half(acc*alpha)
#define HBK 64
#define HPAD 72
#define HASZ (128*HPAD)
#define HBSZ (256*HPAD)
#define NNPAD 264
#define HSTG 3
#define HSMEM (HSTG*(HASZ + HBSZ)*2)     // 165888 bytes (max of both layouts)

template<int EPI, int BL>
__global__ void __launch_bounds__(256, 1) gemm_h(
    const __half* __restrict__ A, int lda,
    const __half* __restrict__ B, int ldb,
    float* __restrict__ Cf, __half* __restrict__ Ch, int ldc,
    int Kdim, int zDiv,
    size_t aSh, size_t aSp, size_t bSh, size_t bSp, size_t cSh, size_t cSp,
    const float* __restrict__ bias, const float* __restrict__ extra,
    float alpha)
{
    extern __shared__ __half smh[];
    __half* As = smh;                    // [HSTG][128][HPAD]
    __half* Bs = smh + HSTG*HASZ;
    constexpr int BSZ = (BL==1) ? (HBK*NNPAD) : HBSZ;

    const int zh = blockIdx.z / zDiv, zp = blockIdx.z % zDiv;
    A += (size_t)zh*aSh + (size_t)zp*aSp;
    B += (size_t)zh*bSh + (size_t)zp*bSp;
    const size_t coff = (size_t)zh*cSh + (size_t)zp*cSp;

    const int tid = threadIdx.x, lane = tid & 31, warp = tid >> 5;
    const int wm = warp >> 2, wn = warp & 3;
    const int g = lane >> 2, t = lane & 3;
    const int m0 = blockIdx.y * 128, n0 = blockIdx.x * 256;

    const uint32_t As_u = (uint32_t)__cvta_generic_to_shared(As);
    const uint32_t Bs_u = (uint32_t)__cvta_generic_to_shared(Bs);
    const uint32_t a_off = (uint32_t)(((wm*64 + (lane & 15))*HPAD + (lane >> 4)*8) * 2);
    uint32_t b_off;
    if (BL==0)
        b_off = (uint32_t)(((wn*64 + ((lane >> 4) << 3) + (lane & 7))*HPAD + ((lane >> 3) & 1)*8) * 2);
    else
        b_off = (uint32_t)((((lane & 7) + ((lane >> 3) & 1)*8)*NNPAD + ((lane >> 4) & 1)*8 + wn*64) * 2);

    float acc[4][8][4];
    #pragma unroll
    for (int i=0;i<4;i++)
        #pragma unroll
        for (int j=0;j<8;j++)
            #pragma unroll
            for (int e=0;e<4;e++) acc[i][j][e]=0.f;

    auto loadT = [&](int kt, int b){
        #pragma unroll
        for (int i=0;i<4;i++){
            int c = tid + i*256; int row = c>>3, k8 = c&7;
            cpa16h(As + b*HASZ + row*HPAD + k8*8,
                   A + (size_t)(m0+row)*lda + kt*HBK + k8*8);
        }
        if (BL==0){
            #pragma unroll
            for (int i=0;i<8;i++){
                int c = tid + i*256; int row = c>>3, k8 = c&7;
                cpa16h(Bs + b*BSZ + row*HPAD + k8*8,
                       B + (size_t)(n0+row)*ldb + kt*HBK + k8*8);
            }
        } else {
            #pragma unroll
            for (int i=0;i<8;i++){
                int c = tid + i*256; int kr = c>>5, ch = c&31;
                cpa16h(Bs + b*BSZ + kr*NNPAD + ch*8,
                       B + (size_t)(kt*HBK+kr)*ldb + n0 + ch*8);
            }
        }
        asm volatile("cp.async.commit_group;\n");
    };

    const int nk = Kdim/HBK;
    loadT(0, 0);
    loadT(1, 1);

    int slot = 0;
    for (int kt=0; kt<nk; kt++){
        if (kt+1 < nk){
            asm volatile("cp.async.wait_group 1;\n");
        } else {
            asm volatile("cp.async.wait_group 0;\n");   // drain: newest group is THIS tile
        }
        __syncthreads();

        const uint32_t Au = As_u + (uint32_t)(slot*HASZ*2);
        const uint32_t Bu = Bs_u + (uint32_t)(slot*BSZ*2);
        #pragma unroll
        for (int ks=0; ks<4; ks++){
            uint32_t af[4][4], bf[8][2];
            #pragma unroll
            for (int mi=0;mi<4;mi++){
                uint32_t ad = Au + a_off + (uint32_t)(mi*16*HPAD*2 + ks*32);
                asm volatile("ldmatrix.sync.aligned.m8n8.x4.shared.b16 {%0,%1,%2,%3}, [%4];"
                    : "=r"(af[mi][0]),"=r"(af[mi][1]),"=r"(af[mi][2]),"=r"(af[mi][3]) : "r"(ad));
            }
            #pragma unroll
            for (int np=0;np<4;np++){
                if (BL==0){
                    uint32_t bd = Bu + b_off + (uint32_t)(np*16*HPAD*2 + ks*32);
                    asm volatile("ldmatrix.sync.aligned.m8n8.x4.shared.b16 {%0,%1,%2,%3}, [%4];"
                        : "=r"(bf[2*np][0]),"=r"(bf[2*np][1]),"=r"(bf[2*np+1][0]),"=r"(bf[2*np+1][1]) : "r"(bd));
                } else {
                    uint32_t bd = Bu + b_off + (uint32_t)((ks*16*NNPAD + np*16)*2);
                    asm volatile("ldmatrix.sync.aligned.m8n8.x4.trans.shared.b16 {%0,%1,%2,%3}, [%4];"
                        : "=r"(bf[2*np][0]),"=r"(bf[2*np][1]),"=r"(bf[2*np+1][0]),"=r"(bf[2*np+1][1]) : "r"(bd));
                }
            }
            #pragma unroll
            for (int mi=0;mi<4;mi++)
                #pragma unroll
                for (int ni=0;ni<8;ni++)
                    asm volatile(
                        "mma.sync.aligned.m16n8k16.row.col.f32.f16.f16.f32 "
                        "{%0,%1,%2,%3},{%4,%5,%6,%7},{%8,%9},{%0,%1,%2,%3};\n"
                        : "+f"(acc[mi][ni][0]), "+f"(acc[mi][ni][1]),
                          "+f"(acc[mi][ni][2]), "+f"(acc[mi][ni][3])
                        : "r"(af[mi][0]),"r"(af[mi][1]),"r"(af[mi][2]),"r"(af[mi][3]),
                          "r"(bf[ni][0]),"r"(bf[ni][1]));
        }

        if (kt+2 < nk){
            int s2 = slot + 2; if (s2 >= HSTG) s2 -= HSTG;
            loadT(kt+2, s2);
        }
        if (++slot == HSTG) slot = 0;
    }

    #pragma unroll
    for (int mi=0;mi<4;mi++){
        #pragma unroll
        for (int half_=0; half_<2; half_++){
            const int row = m0 + wm*64 + mi*16 + g + half_*8;
            #pragma unroll
            for (int ni=0;ni<8;ni++){
                const int col = n0 + wn*64 + ni*8 + t*2;
                float v0 = acc[mi][ni][half_*2 + 0];
                float v1 = acc[mi][ni][half_*2 + 1];
                if (EPI==0){
                    float2 o; o.x=v0*alpha; o.y=v1*alpha;
                    *reinterpret_cast<float2*>(Cf + coff + (size_t)row*ldc + col) = o;
                } else if (EPI==1){
                    float x0 = v0 + bias[col], x1 = v1 + bias[col+1];
                    float o0 = 0.5f*x0*(1.f + erff(x0*0.70710678118654752f));
                    float o1 = 0.5f*x1*(1.f + erff(x1*0.70710678118654752f));
                    *reinterpret_cast<__half2*>(Ch + coff + (size_t)row*ldc + col) = __floats2half2_rn(o0, o1);
                } else if (EPI==2){
                    float x0 = v0 + bias[col], x1 = v1 + bias[col+1];
                    const float2 ex = *reinterpret_cast<const float2*>(extra + (size_t)row*DF + col);
                    *reinterpret_cast<__half2*>(Ch + coff + (size_t)row*ldc + col) =
                        __floats2half2_rn(ex.x * sigf(x0), ex.y * sigf(x1));
                } else {
                    *reinterpret_cast<__half2*>(Ch + coff + (size_t)row*ldc + col) =
                        __floats2half2_rn(v0*alpha, v1*alpha);
                }
            }
        }
    }
}

// ---------------- small kernels ----------------
__global__ void w2h_kernel(const float* __restrict__ w, __half* __restrict__ o){
    size_t i = ((size_t)blockIdx.x*256 + threadIdx.x)*4;
    float4 v = *reinterpret_cast<const float4*>(w + i);
    *reinterpret_cast<__half2*>(o + i)     = __floats2half2_rn(v.x, v.y);
    *reinterpret_cast<__half2*>(o + i + 2) = __floats2half2_rn(v.z, v.w);
}

__global__ void w1b0_kernel(const float* __restrict__ W1w, __half* __restrict__ o){
    size_t e = ((size_t)blockIdx.x*256 + threadIdx.x)*4;
    int r = (int)(e / DF), c = (int)(e % DF);
    float4 v = *reinterpret_cast<const float4*>(W1w + (size_t)r*3*DF + c);
    *reinterpret_cast<__half2*>(o + e)     = __floats2half2_rn(v.x, v.y);
    *reinterpret_cast<__half2*>(o + e + 2) = __floats2half2_rn(v.z, v.w);
}

__global__ void reduce_text_kernel(const float* __restrict__ text){
    int d = blockIdx.x*256 + threadIdx.x;
    float s = 0.f;
    for (int tt=0; tt<TT; tt++) s += text[(size_t)tt*DF + d];
    g_tg[d] = s * (1.f/TT);
}

__global__ void reduce_feats_kernel(const float* __restrict__ feats){
    int d = blockIdx.x*256 + threadIdx.x;
    int l = blockIdx.y;
    const float* p = feats + (size_t)l*NTOK*DF + d;
    float s = 0.f;
    for (int n=0;n<NTOK;n++) s += p[(size_t)n*DF];
    g_y[l*DF + d] = s * (1.f/NTOK);
}

__global__ void base_kernel(const float* __restrict__ W1w, const float* __restrict__ W1b){
    int warp = threadIdx.x >> 5, lane = threadIdx.x & 31;
    int r = blockIdx.x*8 + warp;
    int l = blockIdx.y;
    const float* wy = W1w + (size_t)r*(3*DF) + DF;
    const float* wt = wy + DF;
    const float* y  = g_y + l*DF;
    float acc = 0.f;
    for (int j = lane*4; j < DF; j += 128){
        float4 a = *(const float4*)(wy + j);
        float4 b = *(const float4*)(y + j);
        acc += a.x*b.x + a.y*b.y + a.z*b.z + a.w*b.w;
        float4 c = *(const float4*)(wt + j);
        float4 d = *(const float4*)(g_tg + j);
        acc += c.x*d.x + c.y*d.y + c.z*d.z + c.w*d.w;
    }
    acc = warp_sum(acc);
    if (lane==0) g_base[l*RR + r] = acc + W1b[r];
}

__global__ void dsu_init_kernel(){
    int i = blockIdx.x*256 + threadIdx.x;
    g_c[i] = 0.f; g_cpn[i] = 0.5f;
}

__global__ void s_kernel(int l){
    int r = blockIdx.x*8 + (threadIdx.x>>5);
    int lane = threadIdx.x & 31;
    const __half* w = g_w1b0h + (size_t)r*DF;
    float acc = 0.f;
    for (int j=lane*8; j<DF; j+=256)
        acc += dot8h(*reinterpret_cast<const uint4*>(w + j), g_cpn + j);
    acc = warp_sum(acc);
    if (lane==0){ float v = acc + g_base[l*RR + r]; g_s[r] = v > 0.f ? v : 0.f; }
}

__global__ void c_kernel(const float* __restrict__ Wcb, const float* __restrict__ bc,
                         const float* __restrict__ Wib, const float* __restrict__ bi,
                         const float* __restrict__ Wfb, const float* __restrict__ bfb,
                         int l){
    int d = blockIdx.x*8 + (threadIdx.x>>5);
    int lane = threadIdx.x & 31;
    float ac=0.f, ai=0.f, afv=0.f;
    for (int j=lane*8; j<RR; j+=256){
        ac  += dot8h(*reinterpret_cast<const uint4*>(g_wch + (size_t)d*RR + j), g_s + j);
        ai  += dot8h(*reinterpret_cast<const uint4*>(g_wih + (size_t)d*RR + j), g_s + j);
        afv += dot8h(*reinterpret_cast<const uint4*>(g_wfh + (size_t)d*RR + j), g_s + j);
    }
    ac = warp_sum(ac); ai = warp_sum(ai); afv = warp_sum(afv);
    if (lane==0){
        float ct = tanhf(ac + Wcb[d] + bc[d]);
        float ig = sigf(ai + Wib[d] + bi[d]);
        float fg = sigf(afv + Wfb[d] + bfb[d]);
        float cn = fg*g_c[d] + ig*ct;
        g_c[d] = cn;
        g_cpn[d] = sigf(cn);
        g_ctx[l*DF + d] = cn;
    }
}

__global__ void addctx_h_kernel(const float* __restrict__ feats){
    size_t n4 = (size_t)STOT*DF/4;
    const float4* f4 = (const float4*)feats;
    const float4* c4 = (const float4*)g_ctx;
    for (size_t i = (size_t)blockIdx.x*blockDim.x + threadIdx.x; i < n4; i += (size_t)gridDim.x*blockDim.x){
        size_t row = i >> 10;
        int l = (int)(row / NTOK);
        int d4 = (int)(i & 1023);
        float4 a = f4[i], b = c4[l*1024 + d4];
        *reinterpret_cast<__half2*>(g_xh + i*4)     = __floats2half2_rn(a.x+b.x, a.y+b.y);
        *reinterpret_cast<__half2*>(g_xh + i*4 + 2) = __floats2half2_rn(a.z+b.z, a.w+b.w);
    }
}

// LayerNorm: src fp32 (P-way partial) or srch half (P=1); out fp32 or half
__global__ void ln_kernel(const float* __restrict__ src, const __half* __restrict__ srch,
                          size_t pstride, int P,
                          const float* __restrict__ bias,
                          const float* __restrict__ gam, const float* __restrict__ bet,
                          float* __restrict__ dst, __half* __restrict__ dsth){
    int row = blockIdx.x, tid = threadIdx.x;
    float x[16];
    float s=0.f, sq=0.f;
    #pragma unroll
    for (int j=0;j<16;j++){
        int col = tid + j*256;
        size_t base = (size_t)row*DF + col;
        float v = bias[col];
        if (srch){
            v += __half2float(srch[base]);
        } else {
            for (int p=0;p<P;p++) v += src[(size_t)p*pstride + base];
        }
        x[j]=v; s+=v; sq+=v*v;
    }
    __shared__ float r1[256], r2[256];
    r1[tid]=s; r2[tid]=sq; __syncthreads();
    for (int o=128;o;o>>=1){ if(tid<o){ r1[tid]+=r1[tid+o]; r2[tid]+=r2[tid+o]; } __syncthreads(); }
    float mean = r1[0]*(1.f/DF);
    float var  = r2[0]*(1.f/DF) - mean*mean;
    float rstd = rsqrtf(var + 1e-5f);
    #pragma unroll
    for (int j=0;j<16;j++){
        int col = tid + j*256;
        float o = (x[j]-mean)*rstd*gam[col] + bet[col];
        if (dsth) dsth[(size_t)row*DF + col] = __float2half(o);
        else      dst [(size_t)row*DF + col] = o;
    }
}

__global__ void softmax_kernel(){
    int row = blockIdx.x, tid = threadIdx.x;
    const __half* p = g_scoresh + (size_t)row*STOT;
    __half* q = g_attnh + (size_t)row*STOT;
    __shared__ float red[256];
    float m = -1e30f;
    for (int j=tid; j<STOT; j+=256) m = fmaxf(m, __half2float(p[j]));
    red[tid]=m; __syncthreads();
    for (int o=128;o;o>>=1){ if(tid<o) red[tid]=fmaxf(red[tid],red[tid+o]); __syncthreads(); }
    m = red[0]; __syncthreads();
    float s = 0.f;
    for (int j=tid; j<STOT; j+=256){ s += expf(__half2float(p[j])-m); }
    red[tid]=s; __syncthreads();
    for (int o=128;o;o>>=1){ if(tid<o) red[tid]+=red[tid+o]; __syncthreads(); }
    float inv = 1.f/red[0];
    for (int j=tid; j<STOT; j+=256) q[j] = __float2half(expf(__half2float(p[j])-m)*inv);
}

__global__ void avreduce_kernel(){
    int i = blockIdx.x*256 + threadIdx.x;
    float s = 0.f;
    #pragma unroll
    for (int p=0;p<NSPL2;p++) s += g_avpart[(size_t)p*TT*DF + i];
    g_atth[i] = __float2half(s);
}

__global__ void t2h_kernel(const float* __restrict__ in, __half* __restrict__ o){
    size_t i = ((size_t)blockIdx.x*256 + threadIdx.x)*4;
    float4 v = *reinterpret_cast<const float4*>(in + i);
    *reinterpret_cast<__half2*>(o + i)     = __floats2half2_rn(v.x, v.y);
    *reinterpret_cast<__half2*>(o + i + 2) = __floats2half2_rn(v.z, v.w);
}

// ---------------- host launch ----------------
extern "C" void kernel_launch(void* const* d_in, const int* in_sizes, int n_in,
                              void* d_out, int out_size) {
    const float* text = (const float*)d_in[0];
    const float* feats= (const float*)d_in[1];
    const float* W1_w = (const float*)d_in[2];
    const float* W1_b = (const float*)d_in[3];
    const float* Wc_w = (const float*)d_in[4];
    const float* Wc_b = (const float*)d_in[5];
    const float* Wi_w = (const float*)d_in[6];
    const float* Wi_b = (const float*)d_in[7];
    const float* Wf_w = (const float*)d_in[8];
    const float* Wf_b = (const float*)d_in[9];
    const float* bc   = (const float*)d_in[10];
    const float* bi   = (const float*)d_in[11];
    const float* bfp  = (const float*)d_in[12];
    const float* g1_w = (const float*)d_in[13];
    const float* g1_b = (const float*)d_in[14];
    const float* g2_w = (const float*)d_in[15];
    const float* g2_b = (const float*)d_in[16];
    const float* Wq_w = (const float*)d_in[17];
    const float* Wq_b = (const float*)d_in[18];
    const float* Wk_w = (const float*)d_in[19];
    const float* Wk_b = (const float*)d_in[20];
    const float* Wo_w = (const float*)d_in[21];
    const float* Wo_b = (const float*)d_in[22];
    const float* qn_g = (const float*)d_in[23];
    const float* qn_b = (const float*)d_in[24];
    const float* kn_g = (const float*)d_in[25];
    const float* kn_b = (const float*)d_in[26];
    const float* on_g = (const float*)d_in[27];
    const float* on_b = (const float*)d_in[28];
    float* out = (float*)d_out;

    float *p_qpart, *p_opart, *p_avpart;
    __half *p_w1h, *p_w2h, *p_wkh, *p_wqh, *p_woh, *p_xh, *p_hh, *p_rh, *p_kh, *p_qh, *p_texth, *p_atth, *p_scoresh, *p_attnh;
    __half *p_w1b0h, *p_wch, *p_wih, *p_wfh;
    cudaGetSymbolAddress((void**)&p_qpart, g_qpart);
    cudaGetSymbolAddress((void**)&p_opart, g_opart);
    cudaGetSymbolAddress((void**)&p_avpart, g_avpart);
    cudaGetSymbolAddress((void**)&p_w1h, g_w1h);
    cudaGetSymbolAddress((void**)&p_w2h, g_w2h);
    cudaGetSymbolAddress((void**)&p_wkh, g_wkh);
    cudaGetSymbolAddress((void**)&p_wqh, g_wqh);
    cudaGetSymbolAddress((void**)&p_woh, g_woh);
    cudaGetSymbolAddress((void**)&p_xh, g_xh);
    cudaGetSymbolAddress((void**)&p_hh, g_hh);
    cudaGetSymbolAddress((void**)&p_rh, g_rh);
    cudaGetSymbolAddress((void**)&p_kh, g_kh);
    cudaGetSymbolAddress((void**)&p_qh, g_qh);
    cudaGetSymbolAddress((void**)&p_texth, g_texth);
    cudaGetSymbolAddress((void**)&p_atth, g_atth);
    cudaGetSymbolAddress((void**)&p_scoresh, g_scoresh);
    cudaGetSymbolAddress((void**)&p_attnh, g_attnh);
    cudaGetSymbolAddress((void**)&p_w1b0h, g_w1b0h);
    cudaGetSymbolAddress((void**)&p_wch, g_wch);
    cudaGetSymbolAddress((void**)&p_wih, g_wih);
    cudaGetSymbolAddress((void**)&p_wfh, g_wfh);

    cudaFuncSetAttribute((const void*)gemm_h<0,0>, cudaFuncAttributeMaxDynamicSharedMemorySize, HSMEM);
    cudaFuncSetAttribute((const void*)gemm_h<1,0>, cudaFuncAttributeMaxDynamicSharedMemorySize, HSMEM);
    cudaFuncSetAttribute((const void*)gemm_h<2,0>, cudaFuncAttributeMaxDynamicSharedMemorySize, HSMEM);
    cudaFuncSetAttribute((const void*)gemm_h<3,0>, cudaFuncAttributeMaxDynamicSharedMemorySize, HSMEM);
    cudaFuncSetAttribute((const void*)gemm_h<0,1>, cudaFuncAttributeMaxDynamicSharedMemorySize, HSMEM);

    // 1) means + weight converts
    reduce_text_kernel<<<DF/256, 256>>>(text);
    reduce_feats_kernel<<<dim3(DF/256, LL), 256>>>(feats);
    base_kernel<<<dim3(RR/8, LL), 256>>>(W1_w, W1_b);
    dsu_init_kernel<<<DF/256, 256>>>();
    const int wblocks = (DF*DF/4)/256;
    w2h_kernel<<<wblocks, 256>>>(g1_w, p_w1h);
    w2h_kernel<<<wblocks, 256>>>(g2_w, p_w2h);
    w2h_kernel<<<wblocks, 256>>>(Wk_w, p_wkh);
    w2h_kernel<<<wblocks, 256>>>(Wq_w, p_wqh);
    w2h_kernel<<<wblocks, 256>>>(Wo_w, p_woh);
    t2h_kernel<<<(TT*DF/4)/256, 256>>>(text, p_texth);
    const int dblocks = (DF*RR/4)/256;
    w1b0_kernel<<<dblocks, 256>>>(W1_w, p_w1b0h);
    w2h_kernel<<<dblocks, 256>>>(Wc_w, p_wch);
    w2h_kernel<<<dblocks, 256>>>(Wi_w, p_wih);
    w2h_kernel<<<dblocks, 256>>>(Wf_w, p_wfh);

    // 2) DSU recurrence (serial, fp16 weights)
    for (int l=0; l<LL; l++){
        s_kernel<<<RR/8, 256>>>(l);
        c_kernel<<<DF/8, 256>>>(Wc_b, bc, Wi_b, bi, Wf_b, bfp, l);
    }

    // 3) spatial gate
    addctx_h_kernel<<<2048, 256>>>(feats);
    dim3 bg(DF/256, STOT/128);
    gemm_h<1,0><<<bg, 256, HSMEM>>>(p_xh, DF, p_w1h, DF, nullptr, p_hh, DF, DF, 1,
        0,0,0,0,0,0, g1_b, nullptr, 1.f);
    gemm_h<2,0><<<bg, 256, HSMEM>>>(p_hh, DF, p_w2h, DF, nullptr, p_rh, DF, DF, 1,
        0,0,0,0,0,0, g2_b, feats, 1.f);

    // 4) Q projection (fp16, split-K 8) + LN -> half
    gemm_h<0,0><<<dim3(DF/256, 1, QSPL), 256, HSMEM>>>(
        p_texth, DF, p_wqh, DF, p_qpart, nullptr, DF, QKS, QSPL,
        0, QKS, 0, QKS, 0, (size_t)TT*DF, nullptr, nullptr, 1.f);
    ln_kernel<<<TT, 256>>>(p_qpart, nullptr, (size_t)TT*DF, QSPL, Wq_b, qn_g, qn_b, nullptr, p_qh);

    // 5) K projection (fp16, half out into xh) + LN -> half
    gemm_h<3,0><<<bg, 256, HSMEM>>>(p_rh, DF, p_wkh, DF, nullptr, p_xh, DF, DF, 1,
        0,0,0,0,0,0, nullptr, nullptr, 1.f);
    ln_kernel<<<STOT, 256>>>(nullptr, p_xh, 0, 1, Wk_b, kn_g, kn_b, nullptr, p_kh);

    // 6) scores = Q_h @ K_h^T / sqrt(HD*L) -> half
    float alpha = 1.0f / sqrtf((float)HDIM * (float)LL);
    gemm_h<3,0><<<dim3(STOT/256, 1, NH), 256, HSMEM>>>(
        p_qh, DF, p_kh, DF, nullptr, p_scoresh, STOT, HDIM, 1,
        512, 0, 512, 0, (size_t)TT*STOT, 0, nullptr, nullptr, alpha);

    // 7) softmax (half in) -> half attn
    softmax_kernel<<<NH*TT, 256>>>();

    // 8) att = attn @ V  (fp16 NN via trans-ldmatrix, split-K 8) -> half att
    gemm_h<0,1><<<dim3(HDIM/256, 1, NH*NSPL2), 256, HSMEM>>>(
        p_attnh, STOT, p_rh, DF, p_avpart, nullptr, DF, KS2, NSPL2,
        (size_t)TT*STOT, KS2, HDIM, (size_t)KS2*DF, 512, (size_t)TT*DF,
        nullptr, nullptr, 1.f);
    avreduce_kernel<<<TT*DF/256, 256>>>();

    // 9) out = LN(att @ Wo^T + b)  (fp16 split-K 8)
    gemm_h<0,0><<<dim3(DF/256, 1, QSPL), 256, HSMEM>>>(
        p_atth, DF, p_woh, DF, p_opart, nullptr, DF, QKS, QSPL,
        0, QKS, 0, QKS, 0, (size_t)TT*DF, nullptr, nullptr, 1.f);
    ln_kernel<<<TT, 256>>>(p_opart, nullptr, (size_t)TT*DF, QSPL, Wo_b, on_g, on_b, out, nullptr);

    (void)in_sizes; (void)n_in; (void)out_size;
}